// round 6
// baseline (speedup 1.0000x reference)
#include <cuda_runtime.h>
#include <cstdint>
#include <cstddef>

#define BB 32
#define TT 2048
#define DD 512
#define UU 32
#define LOG2E 1.4426950408889634f

// Scratch (no cudaMalloc allowed): e2/alpha/beta in log2 units, [B,T,U] fp32.
__device__ float g_e2[BB * TT * UU];
__device__ float g_alpha[BB * TT * UU];
__device__ float g_beta[BB * TT * UU];

__device__ __forceinline__ float ex2a(float x) {
    float y; asm("ex2.approx.ftz.f32 %0, %1;" : "=f"(y) : "f"(x)); return y;
}
__device__ __forceinline__ float lg2a(float x) {
    float y; asm("lg2.approx.ftz.f32 %0, %1;" : "=f"(y) : "f"(x)); return y;
}
__device__ __forceinline__ unsigned long long pk2(float a, float b) {
    unsigned long long r; asm("mov.b64 %0, {%1, %2};" : "=l"(r) : "f"(a), "f"(b)); return r;
}
__device__ __forceinline__ void fma2(unsigned long long &acc, unsigned long long a, unsigned long long b) {
    asm("fma.rn.f32x2 %0, %1, %2, %0;" : "+l"(acc) : "l"(a), "l"(b));
}
__device__ __forceinline__ float2 up2(unsigned long long v) {
    float2 f; asm("mov.b64 {%0, %1}, %2;" : "=f"(f.x), "=f"(f.y) : "l"(v)); return f;
}

// ---------------------------------------------------------------------------
// K1: e2[row, u] = (X[row,:] @ kernel[:,u] + bias[u] (+boundaries)) * LOG2E
// 1 thread = 1 row x 8 u-columns. Kernel chunk [32d x 32u] staged in smem
// (prescaled by LOG2E); X kept in registers via LDG.128. Packed f32x2 FMA.
// ---------------------------------------------------------------------------
__global__ void __launch_bounds__(256) gemm_e2_kernel(
    const float* __restrict__ X, const float* __restrict__ Kn,
    const float* __restrict__ bias, const float* __restrict__ lb,
    const float* __restrict__ rb)
{
    __shared__ float Ws[32 * UU];  // [d_chunk][u], prescaled by LOG2E

    const int tid = threadIdx.x;
    const int rowLocal = tid >> 2;            // 0..63
    const int u0 = (tid & 3) * 8;             // 0,8,16,24
    const size_t row = (size_t)blockIdx.x * 64 + rowLocal;

    const int sdr = tid >> 3;                 // staging: d-row 0..31
    const int suq = (tid & 7) * 4;            // staging: u-quad

    unsigned long long acc0 = 0ull, acc1 = 0ull, acc2 = 0ull, acc3 = 0ull;

    for (int kc = 0; kc < DD / 32; kc++) {
        __syncthreads();
        // stage kernel chunk, prescaled by LOG2E
        float4 kv = *reinterpret_cast<const float4*>(Kn + (size_t)(kc * 32 + sdr) * UU + suq);
        kv.x *= LOG2E; kv.y *= LOG2E; kv.z *= LOG2E; kv.w *= LOG2E;
        *reinterpret_cast<float4*>(&Ws[sdr * UU + suq]) = kv;
        __syncthreads();

        // X chunk for this row -> registers (lines fully consumed across warp)
        float4 xv[8];
        const float4* xg = reinterpret_cast<const float4*>(X + row * DD + kc * 32);
        #pragma unroll
        for (int q = 0; q < 8; q++) xv[q] = __ldg(&xg[q]);

        #pragma unroll
        for (int q = 0; q < 8; q++) {
            #pragma unroll
            for (int c = 0; c < 4; c++) {
                float xs = (c == 0) ? xv[q].x : (c == 1) ? xv[q].y : (c == 2) ? xv[q].z : xv[q].w;
                unsigned long long xd = pk2(xs, xs);
                int k = q * 4 + c;
                const ulonglong2* wp = reinterpret_cast<const ulonglong2*>(&Ws[k * UU + u0]);
                ulonglong2 wA = wp[0];  // (w[u0],w[u0+1]) , (w[u0+2],w[u0+3])
                ulonglong2 wB = wp[1];  // (w[u0+4],w[u0+5]) , (w[u0+6],w[u0+7])
                fma2(acc0, xd, wA.x);
                fma2(acc1, xd, wA.y);
                fma2(acc2, xd, wB.x);
                fma2(acc3, xd, wB.y);
            }
        }
    }

    const int t = (int)(row & (TT - 1));
    float2 a0 = up2(acc0), a1 = up2(acc1), a2 = up2(acc2), a3 = up2(acc3);
    float o[8] = {a0.x, a0.y, a1.x, a1.y, a2.x, a2.y, a3.x, a3.y};
    #pragma unroll
    for (int j = 0; j < 8; j++) {
        float add = __ldg(bias + u0 + j);
        if (t == 0)      add += __ldg(lb + u0 + j);
        if (t == TT - 1) add += __ldg(rb + u0 + j);
        o[j] += add * LOG2E;
    }
    float4* outp = reinterpret_cast<float4*>(g_e2 + row * UU + u0);
    outp[0] = make_float4(o[0], o[1], o[2], o[3]);
    outp[1] = make_float4(o[4], o[5], o[6], o[7]);
}

// ---------------------------------------------------------------------------
// K2: forward/backward LSE recursion. One warp per (batch, direction).
// lane = u. carry2[u] = log2 Sum_j 2^{carry2_prev[j] - e2[j]} * W[j,u],
// W[j,u] = exp(-chain[j,u]) held per-lane as a register column.
// Normalization: 2-step-stale lane-0 offset (uniform shift, softmax-invariant).
// e2 prefetched at distance 4 (>= L2 latency worth of slack).
// ---------------------------------------------------------------------------
__device__ __forceinline__ void rstep(
    float &ereg, int tc, const float* __restrict__ ep, float* __restrict__ op,
    long stepE, const float (&w)[32], float &carry, float &n1, float &n2)
{
    float f = (carry + n2) - ereg;
    float p = ex2a(f);
    if (tc + 4 < TT) ereg = __ldg(ep + (long)(tc + 4) * stepE);
    float s0 = 0.f, s1 = 0.f, s2 = 0.f, s3 = 0.f;
    #pragma unroll
    for (int j = 0; j < 32; j += 4) {
        s0 = fmaf(__shfl_sync(0xffffffffu, p, j + 0), w[j + 0], s0);
        s1 = fmaf(__shfl_sync(0xffffffffu, p, j + 1), w[j + 1], s1);
        s2 = fmaf(__shfl_sync(0xffffffffu, p, j + 2), w[j + 2], s2);
        s3 = fmaf(__shfl_sync(0xffffffffu, p, j + 3), w[j + 3], s3);
    }
    carry = lg2a((s0 + s1) + (s2 + s3));
    op[(long)tc * stepE] = carry;
    n2 = n1;
    n1 = -__shfl_sync(0xffffffffu, carry, 0);  // consumed 2 steps later -> latency hidden
}

__global__ void __launch_bounds__(32) crf_rec_kernel(const float* __restrict__ chain)
{
    const int lane = threadIdx.x;
    const int b = blockIdx.x & 31;
    const int dir = blockIdx.x >> 5;  // 0 = forward (alpha), 1 = backward (beta)

    // W column for this lane: w[j] = exp(-chain[j, lane]) = 2^(-chain*log2e)
    float w[32];
    #pragma unroll
    for (int j = 0; j < 32; j++)
        w[j] = ex2a(-LOG2E * __ldg(chain + j * UU + lane));

    const long stepE = dir ? -(long)UU : (long)UU;
    const size_t base = (size_t)b * TT * UU + (dir ? (size_t)(TT - 1) * UU : 0) + lane;
    const float* ep = g_e2 + base;
    float* op = (dir ? g_beta : g_alpha) + base;

    float e0 = __ldg(ep);
    float e1 = __ldg(ep + stepE);
    float e2v = __ldg(ep + 2 * stepE);
    float e3 = __ldg(ep + 3 * stepE);

    float carry = 0.f, n1 = 0.f, n2 = 0.f;
    for (int t = 0; t < TT; t += 4) {
        rstep(e0,  t,     ep, op, stepE, w, carry, n1, n2);
        rstep(e1,  t + 1, ep, op, stepE, w, carry, n1, n2);
        rstep(e2v, t + 2, ep, op, stepE, w, carry, n1, n2);
        rstep(e3,  t + 3, ep, op, stepE, w, carry, n1, n2);
    }
}

// ---------------------------------------------------------------------------
// K3: margin + softmax. 1 warp per (b,t) row, lane = u. Everything is in log2
// units so softmax(margin) = 2^(m2 - max) / sum. Uniform per-row offsets in
// alpha/beta cancel exactly. Memory-bound (~32 MB).
// ---------------------------------------------------------------------------
__global__ void __launch_bounds__(256) crf_soft_kernel(float* __restrict__ out)
{
    const int lane = threadIdx.x & 31;
    const size_t row = (size_t)blockIdx.x * 8 + (threadIdx.x >> 5);
    const int t = (int)(row & (TT - 1));

    float a  = (t > 0)      ? g_alpha[(row - 1) * UU + lane] : 0.f;
    float e  = g_e2[row * UU + lane];
    float bt = (t < TT - 1) ? g_beta[(row + 1) * UU + lane] : 0.f;
    float m = -(a + e + bt);

    float mx = m;
    #pragma unroll
    for (int o = 16; o > 0; o >>= 1) mx = fmaxf(mx, __shfl_xor_sync(0xffffffffu, mx, o));
    float q = ex2a(m - mx);
    float s = q;
    #pragma unroll
    for (int o = 16; o > 0; o >>= 1) s += __shfl_xor_sync(0xffffffffu, s, o);
    out[row * UU + lane] = __fdividef(q, s);
}

// ---------------------------------------------------------------------------
// Inputs (metadata order): X[B,T,D] f32, kernel[D,U] f32, chain_kernel[U,U] f32,
// bias[U] f32, left_boundary[U] f32, right_boundary[U] f32. Output: [B,T,U] f32.
// ---------------------------------------------------------------------------
extern "C" void kernel_launch(void* const* d_in, const int* in_sizes, int n_in,
                              void* d_out, int out_size)
{
    const float* X     = (const float*)d_in[0];
    const float* Kn    = (const float*)d_in[1];
    const float* chain = (const float*)d_in[2];
    const float* bias  = (const float*)d_in[3];
    const float* lb    = (const float*)d_in[4];
    const float* rb    = (const float*)d_in[5];
    float* out = (float*)d_out;

    gemm_e2_kernel<<<(BB * TT) / 64, 256>>>(X, Kn, bias, lb, rb);
    crf_rec_kernel<<<64, 32>>>(chain);             // 32 batches x {fwd,bwd}, concurrent
    crf_soft_kernel<<<(BB * TT) / 8, 256>>>(out);
}

// round 8
// speedup vs baseline: 1.5865x; 1.5865x over previous
#include <cuda_runtime.h>
#include <cstdint>
#include <cstddef>

#define BB 32
#define TT 2048
#define DD 512
#define UU 32
#define LOG2E 1.4426950408889634f

// Scratch (no cudaMalloc allowed): e2/alpha/beta in log2 units, [B,T,U] fp32.
__device__ float g_e2[BB * TT * UU];
__device__ float g_alpha[BB * TT * UU];
__device__ float g_beta[BB * TT * UU];

__device__ __forceinline__ float ex2a(float x) {
    float y; asm("ex2.approx.ftz.f32 %0, %1;" : "=f"(y) : "f"(x)); return y;
}
__device__ __forceinline__ float lg2a(float x) {
    float y; asm("lg2.approx.ftz.f32 %0, %1;" : "=f"(y) : "f"(x)); return y;
}
__device__ __forceinline__ unsigned long long pk2(float a, float b) {
    unsigned long long r; asm("mov.b64 %0, {%1, %2};" : "=l"(r) : "f"(a), "f"(b)); return r;
}
__device__ __forceinline__ void fma2(unsigned long long &acc, unsigned long long a, unsigned long long b) {
    asm("fma.rn.f32x2 %0, %1, %2, %0;" : "+l"(acc) : "l"(a), "l"(b));
}
__device__ __forceinline__ void add2(unsigned long long &a, unsigned long long b) {
    asm("add.rn.f32x2 %0, %0, %1;" : "+l"(a) : "l"(b));
}
__device__ __forceinline__ float2 up2(unsigned long long v) {
    float2 f; asm("mov.b64 {%0, %1}, %2;" : "=f"(f.x), "=f"(f.y) : "l"(v)); return f;
}

// ---------------------------------------------------------------------------
// K1: e2[row,u] = (X[row,:] @ kernel[:,u] + bias (+boundaries)) * LOG2E
// 8 rows x 4 u-cols per thread: W shared-reads amortized 8x over rows
// (R5 kernel was L1=93.8% bound on redundant LDS). Packed f32x2 FMA.
// FIX vs R6: staging loop is 4 float4/thread (1024 total = 128x32 chunk),
// not 16 (which overran Kn by 48KB and wrote 64KB into 16KB of smem).
// ---------------------------------------------------------------------------
#define ROWS_PT 8
#define KCH 128

__global__ void __launch_bounds__(256) gemm_e2_kernel(
    const float* __restrict__ X, const float* __restrict__ Kn,
    const float* __restrict__ bias, const float* __restrict__ lb,
    const float* __restrict__ rb)
{
    __shared__ __align__(16) float Ws[KCH * UU];  // 16 KB, prescaled by LOG2E

    const int tid = threadIdx.x;
    const int u0 = (tid & 7) * 4;                 // 0,4,...,28
    const int rs = tid >> 3;                      // 0..31
    const size_t rowBase = (size_t)blockIdx.x * 256 + rs;

    unsigned long long acc[ROWS_PT][2];
    #pragma unroll
    for (int r = 0; r < ROWS_PT; r++) { acc[r][0] = 0ull; acc[r][1] = 0ull; }

    for (int kc = 0; kc < DD; kc += KCH) {
        __syncthreads();
        // stage 128x32 kernel chunk = 1024 float4 (4 per thread), prescaled
        const float4* kg = reinterpret_cast<const float4*>(Kn + (size_t)kc * UU);
        #pragma unroll
        for (int j = 0; j < 4; j++) {
            int idx = tid + 256 * j;
            float4 v = __ldg(kg + idx);
            v.x *= LOG2E; v.y *= LOG2E; v.z *= LOG2E; v.w *= LOG2E;
            reinterpret_cast<float4*>(Ws)[idx] = v;
        }
        __syncthreads();

        for (int q = 0; q < KCH / 4; q++) {
            float4 xv[ROWS_PT];
            #pragma unroll
            for (int r = 0; r < ROWS_PT; r++)
                xv[r] = __ldg(reinterpret_cast<const float4*>(
                          X + (rowBase + 32 * r) * DD + kc) + q);
            #pragma unroll
            for (int c = 0; c < 4; c++) {
                int k = q * 4 + c;
                ulonglong2 w = *reinterpret_cast<const ulonglong2*>(&Ws[k * UU + u0]);
                #pragma unroll
                for (int r = 0; r < ROWS_PT; r++) {
                    float xs = (c == 0) ? xv[r].x : (c == 1) ? xv[r].y
                             : (c == 2) ? xv[r].z : xv[r].w;
                    unsigned long long xd = pk2(xs, xs);
                    fma2(acc[r][0], xd, w.x);
                    fma2(acc[r][1], xd, w.y);
                }
            }
        }
    }

    float b4[4], l4[4], r4[4];
    #pragma unroll
    for (int j = 0; j < 4; j++) {
        b4[j] = __ldg(bias + u0 + j);
        l4[j] = __ldg(lb + u0 + j);
        r4[j] = __ldg(rb + u0 + j);
    }
    #pragma unroll
    for (int r = 0; r < ROWS_PT; r++) {
        size_t row = rowBase + 32 * r;
        int t = (int)(row & (TT - 1));
        float2 a0 = up2(acc[r][0]), a1 = up2(acc[r][1]);
        float4 o;
        float f0 = (t == 0) ? 1.f : 0.f, f1 = (t == TT - 1) ? 1.f : 0.f;
        o.x = a0.x + (b4[0] + f0 * l4[0] + f1 * r4[0]) * LOG2E;
        o.y = a0.y + (b4[1] + f0 * l4[1] + f1 * r4[1]) * LOG2E;
        o.z = a1.x + (b4[2] + f0 * l4[2] + f1 * r4[2]) * LOG2E;
        o.w = a1.y + (b4[3] + f0 * l4[3] + f1 * r4[3]) * LOG2E;
        *reinterpret_cast<float4*>(g_e2 + row * UU + u0) = o;
    }
}

// ---------------------------------------------------------------------------
// K2: forward/backward LSE recursion, one warp per (batch, direction).
// SHFL broadcast (32/step, MIO-throughput bound) replaced by smem broadcast:
// STS p -> syncwarp -> 8x LDS.128 (all-lane broadcast) -> 16x f32x2 FMA.
// d = (stale lane-0 offset - e_t) precomputed one step early: off crit path.
// ---------------------------------------------------------------------------
__device__ __forceinline__ void rstep(
    float &eslot, const float &enext, float &d, int tc,
    const float* __restrict__ ep, float* __restrict__ op, long stepE,
    const unsigned long long (&w2)[16], float (*pbuf)[32],
    int lane, float &carry, float &n1)
{
    float p = ex2a(carry + d);
    pbuf[tc & 1][lane] = p;
    if (tc + 4 < TT) eslot = __ldg(ep + (long)(tc + 4) * stepE);  // L2-resident prefetch
    d = n1 - enext;               // offset for step tc+1 (n1 = -c0(tc-1) = n2 at tc+1)
    __syncwarp();
    const ulonglong2* pb = reinterpret_cast<const ulonglong2*>(pbuf[tc & 1]);
    unsigned long long a0 = 0ull, a1 = 0ull, a2 = 0ull, a3 = 0ull;
    #pragma unroll
    for (int i = 0; i < 4; i++) {
        ulonglong2 qa = pb[2 * i];        // pairs (p4i,p4i+1),(p4i+2,p4i+3)
        ulonglong2 qb = pb[2 * i + 1];
        fma2(a0, qa.x, w2[4 * i + 0]);
        fma2(a1, qa.y, w2[4 * i + 1]);
        fma2(a2, qb.x, w2[4 * i + 2]);
        fma2(a3, qb.y, w2[4 * i + 3]);
    }
    add2(a0, a1); add2(a2, a3); add2(a0, a2);
    float2 s = up2(a0);
    carry = lg2a(s.x + s.y);
    op[(long)tc * stepE] = carry;
    n1 = -__shfl_sync(0xffffffffu, carry, 0);  // consumed next step, used step after
}

__global__ void __launch_bounds__(32) crf_rec_kernel(const float* __restrict__ chain)
{
    __shared__ __align__(16) float pbuf[2][32];
    const int lane = threadIdx.x;
    const int b = blockIdx.x & 31;
    const int dir = blockIdx.x >> 5;  // 0 = forward (alpha), 1 = backward (beta)

    // w2[j] = ( 2^{-chain[2j,lane]*log2e}, 2^{-chain[2j+1,lane]*log2e} )
    unsigned long long w2[16];
    #pragma unroll
    for (int j = 0; j < 16; j++) {
        float wa = ex2a(-LOG2E * __ldg(chain + (2 * j) * UU + lane));
        float wb = ex2a(-LOG2E * __ldg(chain + (2 * j + 1) * UU + lane));
        w2[j] = pk2(wa, wb);
    }

    const long stepE = dir ? -(long)UU : (long)UU;
    const size_t base = (size_t)b * TT * UU + (dir ? (size_t)(TT - 1) * UU : 0) + lane;
    const float* ep = g_e2 + base;
    float* op = (dir ? g_beta : g_alpha) + base;

    float e0 = __ldg(ep);
    float e1 = __ldg(ep + stepE);
    float e2v = __ldg(ep + 2 * stepE);
    float e3 = __ldg(ep + 3 * stepE);

    float carry = 0.f, n1 = 0.f;
    float d = -e0;  // t=0: n2 = 0

    for (int t = 0; t < TT; t += 4) {
        rstep(e0,  e1,  d, t + 0, ep, op, stepE, w2, pbuf, lane, carry, n1);
        rstep(e1,  e2v, d, t + 1, ep, op, stepE, w2, pbuf, lane, carry, n1);
        rstep(e2v, e3,  d, t + 2, ep, op, stepE, w2, pbuf, lane, carry, n1);
        rstep(e3,  e0,  d, t + 3, ep, op, stepE, w2, pbuf, lane, carry, n1);  // e0 = e_{t+4}
    }
}

// ---------------------------------------------------------------------------
// K3: margin + softmax, 1 warp per (b,t) row. log2 units throughout; uniform
// per-row offsets in alpha/beta cancel exactly. Memory-bound, L2-resident.
// ---------------------------------------------------------------------------
__global__ void __launch_bounds__(256) crf_soft_kernel(float* __restrict__ out)
{
    const int lane = threadIdx.x & 31;
    const size_t row = (size_t)blockIdx.x * 8 + (threadIdx.x >> 5);
    const int t = (int)(row & (TT - 1));

    float a  = (t > 0)      ? g_alpha[(row - 1) * UU + lane] : 0.f;
    float e  = g_e2[row * UU + lane];
    float bt = (t < TT - 1) ? g_beta[(row + 1) * UU + lane] : 0.f;
    float m = -(a + e + bt);

    float mx = m;
    #pragma unroll
    for (int o = 16; o > 0; o >>= 1) mx = fmaxf(mx, __shfl_xor_sync(0xffffffffu, mx, o));
    float q = ex2a(m - mx);
    float s = q;
    #pragma unroll
    for (int o = 16; o > 0; o >>= 1) s += __shfl_xor_sync(0xffffffffu, s, o);
    out[row * UU + lane] = __fdividef(q, s);
}

// ---------------------------------------------------------------------------
// Inputs: X[B,T,D] f32, kernel[D,U] f32, chain_kernel[U,U] f32, bias[U],
// left_boundary[U], right_boundary[U]. Output: [B,T,U] f32.
// ---------------------------------------------------------------------------
extern "C" void kernel_launch(void* const* d_in, const int* in_sizes, int n_in,
                              void* d_out, int out_size)
{
    const float* X     = (const float*)d_in[0];
    const float* Kn    = (const float*)d_in[1];
    const float* chain = (const float*)d_in[2];
    const float* bias  = (const float*)d_in[3];
    const float* lb    = (const float*)d_in[4];
    const float* rb    = (const float*)d_in[5];
    float* out = (float*)d_out;

    gemm_e2_kernel<<<(BB * TT) / 256, 256>>>(X, Kn, bias, lb, rb);
    crf_rec_kernel<<<64, 32>>>(chain);             // 32 batches x {fwd,bwd}
    crf_soft_kernel<<<(BB * TT) / 8, 256>>>(out);
}

// round 9
// speedup vs baseline: 6.0686x; 3.8252x over previous
#include <cuda_runtime.h>
#include <cstdint>
#include <cstddef>

#define BB 32
#define TT 2048
#define DD 512
#define UU 32
#define LOG2E 1.4426950408889634f

// Recursion chunking: 32 chunks of 64 steps, 32-step burn-in (Birkhoff
// contraction tau~0.34/step => init error ~1e-15 after 32 steps, and the
// residual is a per-row uniform shift which softmax cancels exactly).
#define CCH 32
#define LCH (TT / CCH)   // 64
#define HBI 32

// Scratch (no cudaMalloc allowed): e2/alpha/beta in log2 units, [B,T,U] fp32.
__device__ float g_e2[BB * TT * UU];
__device__ float g_alpha[BB * TT * UU];
__device__ float g_beta[BB * TT * UU];

__device__ __forceinline__ float ex2a(float x) {
    float y; asm("ex2.approx.ftz.f32 %0, %1;" : "=f"(y) : "f"(x)); return y;
}
__device__ __forceinline__ float lg2a(float x) {
    float y; asm("lg2.approx.ftz.f32 %0, %1;" : "=f"(y) : "f"(x)); return y;
}
__device__ __forceinline__ unsigned long long pk2(float a, float b) {
    unsigned long long r; asm("mov.b64 %0, {%1, %2};" : "=l"(r) : "f"(a), "f"(b)); return r;
}
__device__ __forceinline__ void fma2(unsigned long long &acc, unsigned long long a, unsigned long long b) {
    asm("fma.rn.f32x2 %0, %1, %2, %0;" : "+l"(acc) : "l"(a), "l"(b));
}
__device__ __forceinline__ void add2(unsigned long long &a, unsigned long long b) {
    asm("add.rn.f32x2 %0, %0, %1;" : "+l"(a) : "l"(b));
}
__device__ __forceinline__ float2 up2(unsigned long long v) {
    float2 f; asm("mov.b64 {%0, %1}, %2;" : "=f"(f.x), "=f"(f.y) : "l"(v)); return f;
}

// ---------------------------------------------------------------------------
// K1: e2[row,u] = (X[row,:] @ kernel[:,u] + bias (+boundaries)) * LOG2E
// Whole W (512x32 = 64KB) staged ONCE in dynamic smem -> no mid-loop barriers;
// X double-buffered in registers (8 rows x 4 u-cols per thread, f32x2 FMA).
// ---------------------------------------------------------------------------
#define ROWS_PT 8

__device__ __forceinline__ void gemm_compute_q(
    int q, const float4 (&xv)[ROWS_PT], const float* __restrict__ Ws,
    int u0, unsigned long long (&acc)[ROWS_PT][2])
{
    #pragma unroll
    for (int c = 0; c < 4; c++) {
        int k = q * 4 + c;
        ulonglong2 w = *reinterpret_cast<const ulonglong2*>(&Ws[k * UU + u0]);
        #pragma unroll
        for (int r = 0; r < ROWS_PT; r++) {
            float xs = (c == 0) ? xv[r].x : (c == 1) ? xv[r].y
                     : (c == 2) ? xv[r].z : xv[r].w;
            unsigned long long xd = pk2(xs, xs);
            fma2(acc[r][0], xd, w.x);
            fma2(acc[r][1], xd, w.y);
        }
    }
}

__global__ void __launch_bounds__(256) gemm_e2_kernel(
    const float* __restrict__ X, const float* __restrict__ Kn,
    const float* __restrict__ bias, const float* __restrict__ lb,
    const float* __restrict__ rb)
{
    extern __shared__ __align__(16) float Ws[];   // DD*UU floats = 64 KB

    const int tid = threadIdx.x;
    const int u0 = (tid & 7) * 4;                 // 0,4,...,28
    const int rs = tid >> 3;                      // 0..31
    const size_t rowBase = (size_t)blockIdx.x * 256 + rs;

    // stage full W: 4096 float4 = 16 per thread, prescaled by LOG2E
    const float4* kg = reinterpret_cast<const float4*>(Kn);
    #pragma unroll
    for (int j = 0; j < 16; j++) {
        int idx = tid + 256 * j;
        float4 v = __ldg(kg + idx);
        v.x *= LOG2E; v.y *= LOG2E; v.z *= LOG2E; v.w *= LOG2E;
        reinterpret_cast<float4*>(Ws)[idx] = v;
    }
    __syncthreads();

    unsigned long long acc[ROWS_PT][2];
    #pragma unroll
    for (int r = 0; r < ROWS_PT; r++) { acc[r][0] = 0ull; acc[r][1] = 0ull; }

    const float4* xg[ROWS_PT];
    #pragma unroll
    for (int r = 0; r < ROWS_PT; r++)
        xg[r] = reinterpret_cast<const float4*>(X + (rowBase + 32 * r) * DD);

    float4 xa[ROWS_PT], xb[ROWS_PT];
    #pragma unroll
    for (int r = 0; r < ROWS_PT; r++) xa[r] = __ldg(xg[r]);

    for (int q = 0; q < DD / 4; q += 2) {
        #pragma unroll
        for (int r = 0; r < ROWS_PT; r++) xb[r] = __ldg(xg[r] + q + 1);
        gemm_compute_q(q, xa, Ws, u0, acc);
        if (q + 2 < DD / 4) {
            #pragma unroll
            for (int r = 0; r < ROWS_PT; r++) xa[r] = __ldg(xg[r] + q + 2);
        }
        gemm_compute_q(q + 1, xb, Ws, u0, acc);
    }

    float b4[4], l4[4], r4[4];
    #pragma unroll
    for (int j = 0; j < 4; j++) {
        b4[j] = __ldg(bias + u0 + j);
        l4[j] = __ldg(lb + u0 + j);
        r4[j] = __ldg(rb + u0 + j);
    }
    #pragma unroll
    for (int r = 0; r < ROWS_PT; r++) {
        size_t row = rowBase + 32 * r;
        int t = (int)(row & (TT - 1));
        float2 a0 = up2(acc[r][0]), a1 = up2(acc[r][1]);
        float f0 = (t == 0) ? 1.f : 0.f, f1 = (t == TT - 1) ? 1.f : 0.f;
        float4 o;
        o.x = a0.x + (b4[0] + f0 * l4[0] + f1 * r4[0]) * LOG2E;
        o.y = a0.y + (b4[1] + f0 * l4[1] + f1 * r4[1]) * LOG2E;
        o.z = a1.x + (b4[2] + f0 * l4[2] + f1 * r4[2]) * LOG2E;
        o.w = a1.y + (b4[3] + f0 * l4[3] + f1 * r4[3]) * LOG2E;
        *reinterpret_cast<float4*>(g_e2 + row * UU + u0) = o;
    }
}

// ---------------------------------------------------------------------------
// K2: chunked forward/backward LSE recursion. One warp per (b, dir, chunk):
// HBI burn-in steps from uniform init (exact for chunk 0), then LCH stored
// steps. Per-step: smem broadcast of p, 16x f32x2 FMA matvec, lg2; stale
// lane-0 normalization (uniform shift, softmax-invariant).
// ---------------------------------------------------------------------------
template <bool STORE>
__device__ __forceinline__ void rstep(
    float &eslot, const float &enext, float &d, int tc, int lpref,
    const float* __restrict__ ep, float* __restrict__ op, long stepE,
    const unsigned long long (&w2)[16], float (*pbuf)[32],
    int lane, float &carry, float &n1)
{
    float p = ex2a(carry + d);
    pbuf[tc & 1][lane] = p;
    if (tc + 4 < lpref) eslot = __ldg(ep + (long)(tc + 4) * stepE);
    d = n1 - enext;               // offset for step tc+1 (2-step-stale lane-0)
    __syncwarp();
    const ulonglong2* pb = reinterpret_cast<const ulonglong2*>(pbuf[tc & 1]);
    unsigned long long a0 = 0ull, a1 = 0ull, a2 = 0ull, a3 = 0ull;
    #pragma unroll
    for (int i = 0; i < 4; i++) {
        ulonglong2 qa = pb[2 * i];
        ulonglong2 qb = pb[2 * i + 1];
        fma2(a0, qa.x, w2[4 * i + 0]);
        fma2(a1, qa.y, w2[4 * i + 1]);
        fma2(a2, qb.x, w2[4 * i + 2]);
        fma2(a3, qb.y, w2[4 * i + 3]);
    }
    add2(a0, a1); add2(a2, a3); add2(a0, a2);
    float2 s = up2(a0);
    carry = lg2a(s.x + s.y);
    if (STORE) op[(long)tc * stepE] = carry;
    n1 = -__shfl_sync(0xffffffffu, carry, 0);
}

__global__ void __launch_bounds__(32) crf_rec_kernel(const float* __restrict__ chain)
{
    __shared__ __align__(16) float pbuf[2][32];
    const int lane = threadIdx.x;
    const int c   = blockIdx.x & (CCH - 1);
    const int bd  = blockIdx.x >> 5;       // CCH == 32
    const int b   = bd & 31;
    const int dir = bd >> 5;               // 0 = forward, 1 = backward

    // w2[j] = ( 2^{-chain[2j,lane]*log2e}, 2^{-chain[2j+1,lane]*log2e} )
    unsigned long long w2[16];
    #pragma unroll
    for (int j = 0; j < 16; j++) {
        float wa = ex2a(-LOG2E * __ldg(chain + (2 * j) * UU + lane));
        float wb = ex2a(-LOG2E * __ldg(chain + (2 * j + 1) * UU + lane));
        w2[j] = pk2(wa, wb);
    }

    const long stepE = dir ? -(long)UU : (long)UU;
    const size_t base = (size_t)b * TT * UU + (dir ? (size_t)(TT - 1) * UU : 0) + lane;
    const float* ep = g_e2 + base;
    float* op = (dir ? g_beta : g_alpha) + base;

    const int l0 = c * LCH;                 // first stored logical step
    const int h  = (c == 0) ? 0 : HBI;      // burn-in length
    const int ls = l0 - h;
    const int lend = l0 + LCH;              // prefetch/store limit

    float e0  = __ldg(ep + (long)(ls + 0) * stepE);
    float e1  = __ldg(ep + (long)(ls + 1) * stepE);
    float e2v = __ldg(ep + (long)(ls + 2) * stepE);
    float e3  = __ldg(ep + (long)(ls + 3) * stepE);

    float carry = 0.f, n1 = 0.f;
    float d = -e0;                          // uniform init (exact for c==0)

    for (int t = ls; t < l0; t += 4) {      // burn-in (no stores)
        rstep<false>(e0,  e1,  d, t + 0, lend, ep, op, stepE, w2, pbuf, lane, carry, n1);
        rstep<false>(e1,  e2v, d, t + 1, lend, ep, op, stepE, w2, pbuf, lane, carry, n1);
        rstep<false>(e2v, e3,  d, t + 2, lend, ep, op, stepE, w2, pbuf, lane, carry, n1);
        rstep<false>(e3,  e0,  d, t + 3, lend, ep, op, stepE, w2, pbuf, lane, carry, n1);
    }
    for (int t = l0; t < lend; t += 4) {    // stored steps
        rstep<true>(e0,  e1,  d, t + 0, lend, ep, op, stepE, w2, pbuf, lane, carry, n1);
        rstep<true>(e1,  e2v, d, t + 1, lend, ep, op, stepE, w2, pbuf, lane, carry, n1);
        rstep<true>(e2v, e3,  d, t + 2, lend, ep, op, stepE, w2, pbuf, lane, carry, n1);
        rstep<true>(e3,  e0,  d, t + 3, lend, ep, op, stepE, w2, pbuf, lane, carry, n1);
    }
}

// ---------------------------------------------------------------------------
// K3: margin + softmax. 8 threads per (b,t) row, 4 u's each (float4 I/O).
// log2 units; uniform per-row offsets in alpha/beta cancel exactly.
// ---------------------------------------------------------------------------
__global__ void __launch_bounds__(256) crf_soft_kernel(float* __restrict__ out)
{
    const int tid = threadIdx.x;
    const int u0 = (tid & 7) * 4;
    const size_t row = (size_t)blockIdx.x * 32 + (tid >> 3);
    const int t = (int)(row & (TT - 1));

    float4 z = make_float4(0.f, 0.f, 0.f, 0.f);
    float4 a  = (t > 0)      ? *reinterpret_cast<const float4*>(g_alpha + (row - 1) * UU + u0) : z;
    float4 e  = *reinterpret_cast<const float4*>(g_e2 + row * UU + u0);
    float4 bt = (t < TT - 1) ? *reinterpret_cast<const float4*>(g_beta + (row + 1) * UU + u0) : z;

    float4 m;
    m.x = -(a.x + e.x + bt.x); m.y = -(a.y + e.y + bt.y);
    m.z = -(a.z + e.z + bt.z); m.w = -(a.w + e.w + bt.w);

    float mx = fmaxf(fmaxf(m.x, m.y), fmaxf(m.z, m.w));
    #pragma unroll
    for (int o = 4; o > 0; o >>= 1) mx = fmaxf(mx, __shfl_xor_sync(0xffffffffu, mx, o));

    float4 p;
    p.x = ex2a(m.x - mx); p.y = ex2a(m.y - mx);
    p.z = ex2a(m.z - mx); p.w = ex2a(m.w - mx);
    float s = (p.x + p.y) + (p.z + p.w);
    #pragma unroll
    for (int o = 4; o > 0; o >>= 1) s += __shfl_xor_sync(0xffffffffu, s, o);

    float inv = __fdividef(1.f, s);
    p.x *= inv; p.y *= inv; p.z *= inv; p.w *= inv;
    *reinterpret_cast<float4*>(out + row * UU + u0) = p;
}

// ---------------------------------------------------------------------------
// Inputs: X[B,T,D] f32, kernel[D,U] f32, chain_kernel[U,U] f32, bias[U],
// left_boundary[U], right_boundary[U]. Output: [B,T,U] f32.
// ---------------------------------------------------------------------------
extern "C" void kernel_launch(void* const* d_in, const int* in_sizes, int n_in,
                              void* d_out, int out_size)
{
    const float* X     = (const float*)d_in[0];
    const float* Kn    = (const float*)d_in[1];
    const float* chain = (const float*)d_in[2];
    const float* bias  = (const float*)d_in[3];
    const float* lb    = (const float*)d_in[4];
    const float* rb    = (const float*)d_in[5];
    float* out = (float*)d_out;

    cudaFuncSetAttribute(gemm_e2_kernel,
                         cudaFuncAttributeMaxDynamicSharedMemorySize,
                         DD * UU * (int)sizeof(float));

    gemm_e2_kernel<<<(BB * TT) / 256, 256, DD * UU * sizeof(float)>>>(X, Kn, bias, lb, rb);
    crf_rec_kernel<<<64 * CCH, 32>>>(chain);       // 2048 warps: (b, dir, chunk)
    crf_soft_kernel<<<(BB * TT) / 32, 256>>>(out);
}

// round 11
// speedup vs baseline: 6.2076x; 1.0229x over previous
#include <cuda_runtime.h>
#include <cuda_bf16.h>
#include <cstdint>
#include <cstddef>

#define BB 32
#define TT 2048
#define DD 512
#define UU 32
#define LOG2E 1.4426950408889634f

// Recursion chunking: 32 chunks of 64 steps, 32-step burn-in (Birkhoff
// contraction tau~0.34/step => init error ~1e-15, a per-row uniform shift
// which the final softmax cancels exactly).
#define CCH 32
#define LCH (TT / CCH)
#define HBI 32

__device__ float g_e2[BB * TT * UU];
__device__ float g_alpha[BB * TT * UU];
__device__ float g_beta[BB * TT * UU];

__device__ __forceinline__ float ex2a(float x) {
    float y; asm("ex2.approx.ftz.f32 %0, %1;" : "=f"(y) : "f"(x)); return y;
}
__device__ __forceinline__ float lg2a(float x) {
    float y; asm("lg2.approx.ftz.f32 %0, %1;" : "=f"(y) : "f"(x)); return y;
}
__device__ __forceinline__ unsigned long long pk2(float a, float b) {
    unsigned long long r; asm("mov.b64 %0, {%1, %2};" : "=l"(r) : "f"(a), "f"(b)); return r;
}
__device__ __forceinline__ void fma2(unsigned long long &acc, unsigned long long a, unsigned long long b) {
    asm("fma.rn.f32x2 %0, %1, %2, %0;" : "+l"(acc) : "l"(a), "l"(b));
}
__device__ __forceinline__ void add2(unsigned long long &a, unsigned long long b) {
    asm("add.rn.f32x2 %0, %0, %1;" : "+l"(a) : "l"(b));
}
__device__ __forceinline__ float2 up2(unsigned long long v) {
    float2 f; asm("mov.b64 {%0, %1}, %2;" : "=f"(f.x), "=f"(f.y) : "l"(v)); return f;
}

// ======================= HMMA GEMM (K1) ====================================
// e2 = LOG2E*(X @ kernel) + (bias [+bounds])*LOG2E via bf16 split:
//   D = Xh*Kh + Xl*Kh + Xh*Kl  (fp32 accum; dropped Xl*Kl ~ 2^-16 rel)
// mma.sync.m16n8k16 (base sm_80+ ISA -> works on plain sm_100 target).
// Per warp: 16 rows x 32 cols. Per CTA (8 warps): 128 rows. Grid = 512.
#define GEMM_THREADS 256
#define NSTEP (DD / 16)        // 32 k-steps

// pack two f32 -> bf16x2 (low half = first arg)
__device__ __forceinline__ uint32_t packbf(float x, float y) {
    __nv_bfloat162 t = __floats2bfloat162_rn(x, y);
    return *reinterpret_cast<uint32_t*>(&t);
}
// split f32 pair into hi/lo bf16x2 pair
__device__ __forceinline__ void splitbf(float x, float y, uint32_t &hi, uint32_t &lo) {
    __nv_bfloat162 h2 = __floats2bfloat162_rn(x, y);
    hi = *reinterpret_cast<uint32_t*>(&h2);
    float2 hf = __bfloat1622float2(h2);
    lo = packbf(x - hf.x, y - hf.y);
}

__device__ __forceinline__ void mma16816(
    float &d0, float &d1, float &d2, float &d3,
    uint32_t a0, uint32_t a1, uint32_t a2, uint32_t a3,
    uint32_t b0, uint32_t b1)
{
    asm volatile(
        "mma.sync.aligned.m16n8k16.row.col.f32.bf16.bf16.f32 "
        "{%0,%1,%2,%3}, {%4,%5,%6,%7}, {%8,%9}, {%0,%1,%2,%3};"
        : "+f"(d0), "+f"(d1), "+f"(d2), "+f"(d3)
        : "r"(a0), "r"(a1), "r"(a2), "r"(a3), "r"(b0), "r"(b1));
}

__global__ void __launch_bounds__(GEMM_THREADS) gemm_mma_kernel(
    const float* __restrict__ X, const float* __restrict__ Kn,
    const float* __restrict__ bias, const float* __restrict__ lb,
    const float* __restrict__ rb)
{
    // B fragments, lane-major for conflict-free LDS.128:
    //   BF[h/l][kstep][q(0,1)][lane] = uint4{ b_q(nt=0..3) }
    extern __shared__ __align__(16) uint4 BF[];      // [2][NSTEP][2][32] = 64 KB
    uint4* BFh = BF;
    uint4* BFl = BF + NSTEP * 2 * 32;

    const int tid = threadIdx.x;
    const int wid = tid >> 5;
    const int lane = tid & 31;
    const int qrow = lane >> 2;          // 0..7
    const int qcol = lane & 3;           // 0..3
    const size_t rowBase = (size_t)blockIdx.x * 128 + wid * 16;

    // ---- stage B fragments (once per CTA); kernel is 64KB, L2-resident ----
    for (int idx = tid; idx < NSTEP * 2 * 32; idx += GEMM_THREADS) {
        int l = idx & 31;
        int kq = idx >> 5;               // kstep*2 + q
        int k = (kq >> 1) * 16 + (l & 3) * 2 + (kq & 1) * 8;
        uint32_t h[4], lo[4];
        #pragma unroll
        for (int nt = 0; nt < 4; nt++) {
            int u = nt * 8 + (l >> 2);
            float x0 = __ldg(Kn + (size_t)k * UU + u) * LOG2E;
            float x1 = __ldg(Kn + (size_t)(k + 1) * UU + u) * LOG2E;
            splitbf(x0, x1, h[nt], lo[nt]);
        }
        BFh[idx] = make_uint4(h[0], h[1], h[2], h[3]);
        BFl[idx] = make_uint4(lo[0], lo[1], lo[2], lo[3]);
    }
    __syncthreads();

    // ---- mainloop: A frags straight from gmem (double-buffered) ----
    const float* x0p = X + (rowBase + qrow) * DD + qcol * 2;        // row, k-lo
    const float* x1p = X + (rowBase + 8 + qrow) * DD + qcol * 2;    // row+8

    float acc[4][4];
    #pragma unroll
    for (int nt = 0; nt < 4; nt++)
        #pragma unroll
        for (int j = 0; j < 4; j++) acc[nt][j] = 0.f;

    float2 cur[4], nxt[4];
    cur[0] = *reinterpret_cast<const float2*>(x0p);
    cur[1] = *reinterpret_cast<const float2*>(x1p);
    cur[2] = *reinterpret_cast<const float2*>(x0p + 8);
    cur[3] = *reinterpret_cast<const float2*>(x1p + 8);

    for (int ks = 0; ks < NSTEP; ks++) {
        if (ks + 1 < NSTEP) {
            int o = (ks + 1) * 16;
            nxt[0] = *reinterpret_cast<const float2*>(x0p + o);
            nxt[1] = *reinterpret_cast<const float2*>(x1p + o);
            nxt[2] = *reinterpret_cast<const float2*>(x0p + o + 8);
            nxt[3] = *reinterpret_cast<const float2*>(x1p + o + 8);
        }
        uint32_t ah[4], al[4];
        #pragma unroll
        for (int j = 0; j < 4; j++) splitbf(cur[j].x, cur[j].y, ah[j], al[j]);

        uint4 bh0 = BFh[(ks * 2 + 0) * 32 + lane];
        uint4 bh1 = BFh[(ks * 2 + 1) * 32 + lane];
        uint4 bl0 = BFl[(ks * 2 + 0) * 32 + lane];
        uint4 bl1 = BFl[(ks * 2 + 1) * 32 + lane];

        const uint32_t* b0h = &bh0.x; const uint32_t* b1h = &bh1.x;
        const uint32_t* b0l = &bl0.x; const uint32_t* b1l = &bl1.x;
        #pragma unroll
        for (int nt = 0; nt < 4; nt++) {
            mma16816(acc[nt][0], acc[nt][1], acc[nt][2], acc[nt][3],
                     ah[0], ah[1], ah[2], ah[3], b0h[nt], b1h[nt]);
            mma16816(acc[nt][0], acc[nt][1], acc[nt][2], acc[nt][3],
                     al[0], al[1], al[2], al[3], b0h[nt], b1h[nt]);
            mma16816(acc[nt][0], acc[nt][1], acc[nt][2], acc[nt][3],
                     ah[0], ah[1], ah[2], ah[3], b0l[nt], b1l[nt]);
        }
        #pragma unroll
        for (int j = 0; j < 4; j++) cur[j] = nxt[j];
    }

    // ---- epilogue: D[row][col], row0 = rowBase+qrow, row1 = +8; col = nt*8+qcol*2
    size_t row0 = rowBase + qrow;
    size_t row1 = row0 + 8;
    int t0 = (int)(row0 & (TT - 1)), t1 = (int)(row1 & (TT - 1));
    float f00 = (t0 == 0) ? 1.f : 0.f, f01 = (t0 == TT - 1) ? 1.f : 0.f;
    float f10 = (t1 == 0) ? 1.f : 0.f, f11 = (t1 == TT - 1) ? 1.f : 0.f;
    #pragma unroll
    for (int nt = 0; nt < 4; nt++) {
        int col = nt * 8 + qcol * 2;
        float bc0 = __ldg(bias + col),     bc1 = __ldg(bias + col + 1);
        float lc0 = __ldg(lb + col),       lc1 = __ldg(lb + col + 1);
        float rc0 = __ldg(rb + col),       rc1 = __ldg(rb + col + 1);
        float2 o0, o1;
        o0.x = acc[nt][0] + (bc0 + f00 * lc0 + f01 * rc0) * LOG2E;
        o0.y = acc[nt][1] + (bc1 + f00 * lc1 + f01 * rc1) * LOG2E;
        o1.x = acc[nt][2] + (bc0 + f10 * lc0 + f11 * rc0) * LOG2E;
        o1.y = acc[nt][3] + (bc1 + f10 * lc1 + f11 * rc1) * LOG2E;
        *reinterpret_cast<float2*>(g_e2 + row0 * UU + col) = o0;
        *reinterpret_cast<float2*>(g_e2 + row1 * UU + col) = o1;
    }
}

// ======================= K2: chunked recursion (unchanged) =================
template <bool STORE>
__device__ __forceinline__ void rstep(
    float &eslot, const float &enext, float &d, int tc, int lpref,
    const float* __restrict__ ep, float* __restrict__ op, long stepE,
    const unsigned long long (&w2)[16], float (*pbuf)[32],
    int lane, float &carry, float &n1)
{
    float p = ex2a(carry + d);
    pbuf[tc & 1][lane] = p;
    if (tc + 4 < lpref) eslot = __ldg(ep + (long)(tc + 4) * stepE);
    d = n1 - enext;
    __syncwarp();
    const ulonglong2* pb = reinterpret_cast<const ulonglong2*>(pbuf[tc & 1]);
    unsigned long long a0 = 0ull, a1 = 0ull, a2 = 0ull, a3 = 0ull;
    #pragma unroll
    for (int i = 0; i < 4; i++) {
        ulonglong2 qa = pb[2 * i];
        ulonglong2 qb = pb[2 * i + 1];
        fma2(a0, qa.x, w2[4 * i + 0]);
        fma2(a1, qa.y, w2[4 * i + 1]);
        fma2(a2, qb.x, w2[4 * i + 2]);
        fma2(a3, qb.y, w2[4 * i + 3]);
    }
    add2(a0, a1); add2(a2, a3); add2(a0, a2);
    float2 s = up2(a0);
    carry = lg2a(s.x + s.y);
    if (STORE) op[(long)tc * stepE] = carry;
    n1 = -__shfl_sync(0xffffffffu, carry, 0);
}

__global__ void __launch_bounds__(32) crf_rec_kernel(const float* __restrict__ chain)
{
    __shared__ __align__(16) float pbuf[2][32];
    const int lane = threadIdx.x;
    const int c   = blockIdx.x & (CCH - 1);
    const int bd  = blockIdx.x >> 5;
    const int b   = bd & 31;
    const int dir = bd >> 5;

    unsigned long long w2[16];
    #pragma unroll
    for (int j = 0; j < 16; j++) {
        float wa = ex2a(-LOG2E * __ldg(chain + (2 * j) * UU + lane));
        float wb = ex2a(-LOG2E * __ldg(chain + (2 * j + 1) * UU + lane));
        w2[j] = pk2(wa, wb);
    }

    const long stepE = dir ? -(long)UU : (long)UU;
    const size_t base = (size_t)b * TT * UU + (dir ? (size_t)(TT - 1) * UU : 0) + lane;
    const float* ep = g_e2 + base;
    float* op = (dir ? g_beta : g_alpha) + base;

    const int l0 = c * LCH;
    const int h  = (c == 0) ? 0 : HBI;
    const int ls = l0 - h;
    const int lend = l0 + LCH;

    float e0  = __ldg(ep + (long)(ls + 0) * stepE);
    float e1  = __ldg(ep + (long)(ls + 1) * stepE);
    float e2v = __ldg(ep + (long)(ls + 2) * stepE);
    float e3  = __ldg(ep + (long)(ls + 3) * stepE);

    float carry = 0.f, n1 = 0.f;
    float d = -e0;

    for (int t = ls; t < l0; t += 4) {
        rstep<false>(e0,  e1,  d, t + 0, lend, ep, op, stepE, w2, pbuf, lane, carry, n1);
        rstep<false>(e1,  e2v, d, t + 1, lend, ep, op, stepE, w2, pbuf, lane, carry, n1);
        rstep<false>(e2v, e3,  d, t + 2, lend, ep, op, stepE, w2, pbuf, lane, carry, n1);
        rstep<false>(e3,  e0,  d, t + 3, lend, ep, op, stepE, w2, pbuf, lane, carry, n1);
    }
    for (int t = l0; t < lend; t += 4) {
        rstep<true>(e0,  e1,  d, t + 0, lend, ep, op, stepE, w2, pbuf, lane, carry, n1);
        rstep<true>(e1,  e2v, d, t + 1, lend, ep, op, stepE, w2, pbuf, lane, carry, n1);
        rstep<true>(e2v, e3,  d, t + 2, lend, ep, op, stepE, w2, pbuf, lane, carry, n1);
        rstep<true>(e3,  e0,  d, t + 3, lend, ep, op, stepE, w2, pbuf, lane, carry, n1);
    }
}

// ======================= K3: margin + softmax (unchanged) ==================
__global__ void __launch_bounds__(256) crf_soft_kernel(float* __restrict__ out)
{
    const int tid = threadIdx.x;
    const int u0 = (tid & 7) * 4;
    const size_t row = (size_t)blockIdx.x * 32 + (tid >> 3);
    const int t = (int)(row & (TT - 1));

    float4 z = make_float4(0.f, 0.f, 0.f, 0.f);
    float4 a  = (t > 0)      ? *reinterpret_cast<const float4*>(g_alpha + (row - 1) * UU + u0) : z;
    float4 e  = *reinterpret_cast<const float4*>(g_e2 + row * UU + u0);
    float4 bt = (t < TT - 1) ? *reinterpret_cast<const float4*>(g_beta + (row + 1) * UU + u0) : z;

    float4 m;
    m.x = -(a.x + e.x + bt.x); m.y = -(a.y + e.y + bt.y);
    m.z = -(a.z + e.z + bt.z); m.w = -(a.w + e.w + bt.w);

    float mx = fmaxf(fmaxf(m.x, m.y), fmaxf(m.z, m.w));
    #pragma unroll
    for (int o = 4; o > 0; o >>= 1) mx = fmaxf(mx, __shfl_xor_sync(0xffffffffu, mx, o));

    float4 p;
    p.x = ex2a(m.x - mx); p.y = ex2a(m.y - mx);
    p.z = ex2a(m.z - mx); p.w = ex2a(m.w - mx);
    float s = (p.x + p.y) + (p.z + p.w);
    #pragma unroll
    for (int o = 4; o > 0; o >>= 1) s += __shfl_xor_sync(0xffffffffu, s, o);

    float inv = __fdividef(1.f, s);
    p.x *= inv; p.y *= inv; p.z *= inv; p.w *= inv;
    *reinterpret_cast<float4*>(out + row * UU + u0) = p;
}

// ===========================================================================
extern "C" void kernel_launch(void* const* d_in, const int* in_sizes, int n_in,
                              void* d_out, int out_size)
{
    const float* X     = (const float*)d_in[0];
    const float* Kn    = (const float*)d_in[1];
    const float* chain = (const float*)d_in[2];
    const float* bias  = (const float*)d_in[3];
    const float* lb    = (const float*)d_in[4];
    const float* rb    = (const float*)d_in[5];
    float* out = (float*)d_out;

    const int bfBytes = 2 * NSTEP * 2 * 32 * (int)sizeof(uint4);   // 64 KB
    cudaFuncSetAttribute(gemm_mma_kernel,
                         cudaFuncAttributeMaxDynamicSharedMemorySize, bfBytes);

    gemm_mma_kernel<<<(BB * TT) / 128, GEMM_THREADS, bfBytes>>>(X, Kn, bias, lb, rb);
    crf_rec_kernel<<<64 * CCH, 32>>>(chain);
    crf_soft_kernel<<<(BB * TT) / 32, 256>>>(out);
}

// round 12
// speedup vs baseline: 8.3464x; 1.3445x over previous
#include <cuda_runtime.h>
#include <cuda_bf16.h>
#include <cstdint>
#include <cstddef>

#define BB 32
#define TT 2048
#define DD 512
#define UU 32
#define LOG2E 1.4426950408889634f

// Recursion chunking: 64 chunks of 32 steps, 16-step burn-in.
// Birkhoff: diam after 1 step <= 2*max|chain| ~ 0.7 (ln units), tau ~ 0.31
// => residual ~ 0.7 * 0.31^15 ~ 2e-8, a per-row uniform shift which the
// final softmax cancels exactly.
#define CCH 64
#define LCH (TT / CCH)   // 32
#define HBI 16

__device__ float g_e2[BB * TT * UU];
__device__ float g_alpha[BB * TT * UU];
__device__ float g_beta[BB * TT * UU];

__device__ __forceinline__ float ex2a(float x) {
    float y; asm("ex2.approx.ftz.f32 %0, %1;" : "=f"(y) : "f"(x)); return y;
}
__device__ __forceinline__ float lg2a(float x) {
    float y; asm("lg2.approx.ftz.f32 %0, %1;" : "=f"(y) : "f"(x)); return y;
}
__device__ __forceinline__ unsigned long long pk2(float a, float b) {
    unsigned long long r; asm("mov.b64 %0, {%1, %2};" : "=l"(r) : "f"(a), "f"(b)); return r;
}
__device__ __forceinline__ void fma2(unsigned long long &acc, unsigned long long a, unsigned long long b) {
    asm("fma.rn.f32x2 %0, %1, %2, %0;" : "+l"(acc) : "l"(a), "l"(b));
}
__device__ __forceinline__ void add2(unsigned long long &a, unsigned long long b) {
    asm("add.rn.f32x2 %0, %0, %1;" : "+l"(a) : "l"(b));
}
__device__ __forceinline__ float2 up2(unsigned long long v) {
    float2 f; asm("mov.b64 {%0, %1}, %2;" : "=f"(f.x), "=f"(f.y) : "l"(v)); return f;
}

// ======================= HMMA GEMM (K1) ====================================
// e2 = LOG2E*(X @ kernel) + (bias [+bounds])*LOG2E via bf16 split:
//   D = Xh*Kh + Xl*Kh + Xh*Kl  (fp32 accum; dropped Xl*Kl ~ 2^-16 rel)
// mma.sync.m16n8k16. Per warp: 16 rows x 32 cols; 8 warps/CTA; grid 512.
// X prefetch: 4-deep register ring (16 outstanding LDG.64/thread) to cover
// DRAM latency -- R11 was latency-bound at 1-deep (DRAM 30.6%, issue 31.6%).
#define GEMM_THREADS 256
#define NSTEP (DD / 16)        // 32 k-steps
#define PFD 4                  // prefetch depth (k-steps)

__device__ __forceinline__ uint32_t packbf(float x, float y) {
    __nv_bfloat162 t = __floats2bfloat162_rn(x, y);
    return *reinterpret_cast<uint32_t*>(&t);
}
__device__ __forceinline__ void splitbf(float x, float y, uint32_t &hi, uint32_t &lo) {
    __nv_bfloat162 h2 = __floats2bfloat162_rn(x, y);
    hi = *reinterpret_cast<uint32_t*>(&h2);
    float2 hf = __bfloat1622float2(h2);
    lo = packbf(x - hf.x, y - hf.y);
}

__device__ __forceinline__ void mma16816(
    float &d0, float &d1, float &d2, float &d3,
    uint32_t a0, uint32_t a1, uint32_t a2, uint32_t a3,
    uint32_t b0, uint32_t b1)
{
    asm volatile(
        "mma.sync.aligned.m16n8k16.row.col.f32.bf16.bf16.f32 "
        "{%0,%1,%2,%3}, {%4,%5,%6,%7}, {%8,%9}, {%0,%1,%2,%3};"
        : "+f"(d0), "+f"(d1), "+f"(d2), "+f"(d3)
        : "r"(a0), "r"(a1), "r"(a2), "r"(a3), "r"(b0), "r"(b1));
}

__global__ void __launch_bounds__(GEMM_THREADS, 2) gemm_mma_kernel(
    const float* __restrict__ X, const float* __restrict__ Kn,
    const float* __restrict__ bias, const float* __restrict__ lb,
    const float* __restrict__ rb)
{
    // B fragments, lane-major for conflict-free LDS.128:
    //   BF[h/l][kstep][q(0,1)][lane] = uint4{ b_q(nt=0..3) }
    extern __shared__ __align__(16) uint4 BF[];      // [2][NSTEP][2][32] = 64 KB
    uint4* BFh = BF;
    uint4* BFl = BF + NSTEP * 2 * 32;

    const int tid = threadIdx.x;
    const int wid = tid >> 5;
    const int lane = tid & 31;
    const int qrow = lane >> 2;          // 0..7
    const int qcol = lane & 3;           // 0..3
    const size_t rowBase = (size_t)blockIdx.x * 128 + wid * 16;

    // ---- stage B fragments (once per CTA); kernel 64KB, L2-resident ----
    for (int idx = tid; idx < NSTEP * 2 * 32; idx += GEMM_THREADS) {
        int l = idx & 31;
        int kq = idx >> 5;               // kstep*2 + q
        int k = (kq >> 1) * 16 + (l & 3) * 2 + (kq & 1) * 8;
        uint32_t h[4], lo[4];
        #pragma unroll
        for (int nt = 0; nt < 4; nt++) {
            int u = nt * 8 + (l >> 2);
            float x0 = __ldg(Kn + (size_t)k * UU + u) * LOG2E;
            float x1 = __ldg(Kn + (size_t)(k + 1) * UU + u) * LOG2E;
            splitbf(x0, x1, h[nt], lo[nt]);
        }
        BFh[idx] = make_uint4(h[0], h[1], h[2], h[3]);
        BFl[idx] = make_uint4(lo[0], lo[1], lo[2], lo[3]);
    }
    __syncthreads();

    const float* x0p = X + (rowBase + qrow) * DD + qcol * 2;        // row, k-lo
    const float* x1p = X + (rowBase + 8 + qrow) * DD + qcol * 2;    // row+8

    float acc[4][4];
    #pragma unroll
    for (int nt = 0; nt < 4; nt++)
        #pragma unroll
        for (int j = 0; j < 4; j++) acc[nt][j] = 0.f;

    // 4-deep prefetch ring
    float2 ring[PFD][4];
    #pragma unroll
    for (int s = 0; s < PFD; s++) {
        int o = s * 16;
        ring[s][0] = *reinterpret_cast<const float2*>(x0p + o);
        ring[s][1] = *reinterpret_cast<const float2*>(x1p + o);
        ring[s][2] = *reinterpret_cast<const float2*>(x0p + o + 8);
        ring[s][3] = *reinterpret_cast<const float2*>(x1p + o + 8);
    }

    #pragma unroll 4
    for (int ks = 0; ks < NSTEP; ks++) {
        const int st = ks & (PFD - 1);
        uint32_t ah[4], al[4];
        #pragma unroll
        for (int j = 0; j < 4; j++) splitbf(ring[st][j].x, ring[st][j].y, ah[j], al[j]);

        if (ks + PFD < NSTEP) {
            int o = (ks + PFD) * 16;
            ring[st][0] = *reinterpret_cast<const float2*>(x0p + o);
            ring[st][1] = *reinterpret_cast<const float2*>(x1p + o);
            ring[st][2] = *reinterpret_cast<const float2*>(x0p + o + 8);
            ring[st][3] = *reinterpret_cast<const float2*>(x1p + o + 8);
        }

        uint4 bh0 = BFh[(ks * 2 + 0) * 32 + lane];
        uint4 bh1 = BFh[(ks * 2 + 1) * 32 + lane];
        uint4 bl0 = BFl[(ks * 2 + 0) * 32 + lane];
        uint4 bl1 = BFl[(ks * 2 + 1) * 32 + lane];

        const uint32_t* b0h = &bh0.x; const uint32_t* b1h = &bh1.x;
        const uint32_t* b0l = &bl0.x; const uint32_t* b1l = &bl1.x;
        #pragma unroll
        for (int nt = 0; nt < 4; nt++) {
            mma16816(acc[nt][0], acc[nt][1], acc[nt][2], acc[nt][3],
                     ah[0], ah[1], ah[2], ah[3], b0h[nt], b1h[nt]);
            mma16816(acc[nt][0], acc[nt][1], acc[nt][2], acc[nt][3],
                     al[0], al[1], al[2], al[3], b0h[nt], b1h[nt]);
            mma16816(acc[nt][0], acc[nt][1], acc[nt][2], acc[nt][3],
                     ah[0], ah[1], ah[2], ah[3], b0l[nt], b1l[nt]);
        }
    }

    // ---- epilogue ----
    size_t row0 = rowBase + qrow;
    size_t row1 = row0 + 8;
    int t0 = (int)(row0 & (TT - 1)), t1 = (int)(row1 & (TT - 1));
    float f00 = (t0 == 0) ? 1.f : 0.f, f01 = (t0 == TT - 1) ? 1.f : 0.f;
    float f10 = (t1 == 0) ? 1.f : 0.f, f11 = (t1 == TT - 1) ? 1.f : 0.f;
    #pragma unroll
    for (int nt = 0; nt < 4; nt++) {
        int col = nt * 8 + qcol * 2;
        float bc0 = __ldg(bias + col),     bc1 = __ldg(bias + col + 1);
        float lc0 = __ldg(lb + col),       lc1 = __ldg(lb + col + 1);
        float rc0 = __ldg(rb + col),       rc1 = __ldg(rb + col + 1);
        float2 o0, o1;
        o0.x = acc[nt][0] + (bc0 + f00 * lc0 + f01 * rc0) * LOG2E;
        o0.y = acc[nt][1] + (bc1 + f00 * lc1 + f01 * rc1) * LOG2E;
        o1.x = acc[nt][2] + (bc0 + f10 * lc0 + f11 * rc0) * LOG2E;
        o1.y = acc[nt][3] + (bc1 + f10 * lc1 + f11 * rc1) * LOG2E;
        *reinterpret_cast<float2*>(g_e2 + row0 * UU + col) = o0;
        *reinterpret_cast<float2*>(g_e2 + row1 * UU + col) = o1;
    }
}

// ======================= K2: chunked recursion =============================
template <bool STORE>
__device__ __forceinline__ void rstep(
    float &eslot, const float &enext, float &d, int tc, int lpref,
    const float* __restrict__ ep, float* __restrict__ op, long stepE,
    const unsigned long long (&w2)[16], float (*pbuf)[32],
    int lane, float &carry, float &n1)
{
    float p = ex2a(carry + d);
    pbuf[tc & 1][lane] = p;
    if (tc + 4 < lpref) eslot = __ldg(ep + (long)(tc + 4) * stepE);
    d = n1 - enext;
    __syncwarp();
    const ulonglong2* pb = reinterpret_cast<const ulonglong2*>(pbuf[tc & 1]);
    unsigned long long a0 = 0ull, a1 = 0ull, a2 = 0ull, a3 = 0ull;
    #pragma unroll
    for (int i = 0; i < 4; i++) {
        ulonglong2 qa = pb[2 * i];
        ulonglong2 qb = pb[2 * i + 1];
        fma2(a0, qa.x, w2[4 * i + 0]);
        fma2(a1, qa.y, w2[4 * i + 1]);
        fma2(a2, qb.x, w2[4 * i + 2]);
        fma2(a3, qb.y, w2[4 * i + 3]);
    }
    add2(a0, a1); add2(a2, a3); add2(a0, a2);
    float2 s = up2(a0);
    carry = lg2a(s.x + s.y);
    if (STORE) op[(long)tc * stepE] = carry;
    n1 = -__shfl_sync(0xffffffffu, carry, 0);
}

__global__ void __launch_bounds__(32) crf_rec_kernel(const float* __restrict__ chain)
{
    __shared__ __align__(16) float pbuf[2][32];
    const int lane = threadIdx.x;
    const int c   = blockIdx.x & (CCH - 1);
    const int bd  = blockIdx.x >> 6;       // CCH == 64
    const int b   = bd & 31;
    const int dir = bd >> 5;

    unsigned long long w2[16];
    #pragma unroll
    for (int j = 0; j < 16; j++) {
        float wa = ex2a(-LOG2E * __ldg(chain + (2 * j) * UU + lane));
        float wb = ex2a(-LOG2E * __ldg(chain + (2 * j + 1) * UU + lane));
        w2[j] = pk2(wa, wb);
    }

    const long stepE = dir ? -(long)UU : (long)UU;
    const size_t base = (size_t)b * TT * UU + (dir ? (size_t)(TT - 1) * UU : 0) + lane;
    const float* ep = g_e2 + base;
    float* op = (dir ? g_beta : g_alpha) + base;

    const int l0 = c * LCH;
    const int h  = (c == 0) ? 0 : HBI;
    const int ls = l0 - h;
    const int lend = l0 + LCH;

    float e0  = __ldg(ep + (long)(ls + 0) * stepE);
    float e1  = __ldg(ep + (long)(ls + 1) * stepE);
    float e2v = __ldg(ep + (long)(ls + 2) * stepE);
    float e3  = __ldg(ep + (long)(ls + 3) * stepE);

    float carry = 0.f, n1 = 0.f;
    float d = -e0;

    for (int t = ls; t < l0; t += 4) {
        rstep<false>(e0,  e1,  d, t + 0, lend, ep, op, stepE, w2, pbuf, lane, carry, n1);
        rstep<false>(e1,  e2v, d, t + 1, lend, ep, op, stepE, w2, pbuf, lane, carry, n1);
        rstep<false>(e2v, e3,  d, t + 2, lend, ep, op, stepE, w2, pbuf, lane, carry, n1);
        rstep<false>(e3,  e0,  d, t + 3, lend, ep, op, stepE, w2, pbuf, lane, carry, n1);
    }
    for (int t = l0; t < lend; t += 4) {
        rstep<true>(e0,  e1,  d, t + 0, lend, ep, op, stepE, w2, pbuf, lane, carry, n1);
        rstep<true>(e1,  e2v, d, t + 1, lend, ep, op, stepE, w2, pbuf, lane, carry, n1);
        rstep<true>(e2v, e3,  d, t + 2, lend, ep, op, stepE, w2, pbuf, lane, carry, n1);
        rstep<true>(e3,  e0,  d, t + 3, lend, ep, op, stepE, w2, pbuf, lane, carry, n1);
    }
}

// ======================= K3: margin + softmax ==============================
__global__ void __launch_bounds__(256) crf_soft_kernel(float* __restrict__ out)
{
    const int tid = threadIdx.x;
    const int u0 = (tid & 7) * 4;
    const size_t row = (size_t)blockIdx.x * 32 + (tid >> 3);
    const int t = (int)(row & (TT - 1));

    float4 z = make_float4(0.f, 0.f, 0.f, 0.f);
    float4 a  = (t > 0)      ? *reinterpret_cast<const float4*>(g_alpha + (row - 1) * UU + u0) : z;
    float4 e  = *reinterpret_cast<const float4*>(g_e2 + row * UU + u0);
    float4 bt = (t < TT - 1) ? *reinterpret_cast<const float4*>(g_beta + (row + 1) * UU + u0) : z;

    float4 m;
    m.x = -(a.x + e.x + bt.x); m.y = -(a.y + e.y + bt.y);
    m.z = -(a.z + e.z + bt.z); m.w = -(a.w + e.w + bt.w);

    float mx = fmaxf(fmaxf(m.x, m.y), fmaxf(m.z, m.w));
    #pragma unroll
    for (int o = 4; o > 0; o >>= 1) mx = fmaxf(mx, __shfl_xor_sync(0xffffffffu, mx, o));

    float4 p;
    p.x = ex2a(m.x - mx); p.y = ex2a(m.y - mx);
    p.z = ex2a(m.z - mx); p.w = ex2a(m.w - mx);
    float s = (p.x + p.y) + (p.z + p.w);
    #pragma unroll
    for (int o = 4; o > 0; o >>= 1) s += __shfl_xor_sync(0xffffffffu, s, o);

    float inv = __fdividef(1.f, s);
    p.x *= inv; p.y *= inv; p.z *= inv; p.w *= inv;
    *reinterpret_cast<float4*>(out + row * UU + u0) = p;
}

// ===========================================================================
extern "C" void kernel_launch(void* const* d_in, const int* in_sizes, int n_in,
                              void* d_out, int out_size)
{
    const float* X     = (const float*)d_in[0];
    const float* Kn    = (const float*)d_in[1];
    const float* chain = (const float*)d_in[2];
    const float* bias  = (const float*)d_in[3];
    const float* lb    = (const float*)d_in[4];
    const float* rb    = (const float*)d_in[5];
    float* out = (float*)d_out;

    const int bfBytes = 2 * NSTEP * 2 * 32 * (int)sizeof(uint4);   // 64 KB
    cudaFuncSetAttribute(gemm_mma_kernel,
                         cudaFuncAttributeMaxDynamicSharedMemorySize, bfBytes);

    gemm_mma_kernel<<<(BB * TT) / 128, GEMM_THREADS, bfBytes>>>(X, Kn, bias, lb, rb);
    crf_rec_kernel<<<64 * CCH, 32>>>(chain);
    crf_soft_kernel<<<(BB * TT) / 32, 256>>>(out);
}